// round 1
// baseline (speedup 1.0000x reference)
#include <cuda_runtime.h>
#include <math.h>

// Problem dims
constexpr int Bd = 8;
constexpr int Sd = 1024;
constexpr int Ed = 1024;
constexpr int Fd = 4096;
constexpr int MTOT = Bd * Sd;        // 8192

// GEMM tile config
constexpr int BM = 128, BN = 128, BK = 16;

// ---------------- scratch (device globals: no allocation allowed) -------------
__device__ float g_q  [(long long)Bd * Sd * Ed];
__device__ float g_k  [(long long)Bd * Sd * Ed];
__device__ float g_v  [(long long)Bd * Sd * Ed];
__device__ float g_at [(long long)Bd * Sd * Sd];   // scores / attn weights (in-place softmax)
__device__ float g_ao [(long long)Bd * Sd * Ed];   // attn output
__device__ float g_tmp[(long long)Bd * Sd * Ed];   // pre-LN buffer
__device__ float g_h1 [(long long)Bd * Sd * Ed];   // LN1 output
__device__ float g_ff [(long long)Bd * Sd * Fd];   // gelu(h1@Wi+bi)

// ---------------- GEMM ---------------------------------------------------------
// C[b] = act( alpha * A[b] @ B[b](^T if TRANSB) + bias + resid )
// Row-major. All dims multiples of tiles (M%128==0, N%128==0, K%16==0) for this problem.
// ACT: 0 = none, 1 = exact GELU.
template<bool TRANSB, int ACT>
__global__ void __launch_bounds__(256)
gemm_kernel(const float* __restrict__ A, const float* __restrict__ Bm,
            const float* __restrict__ bias, const float* __restrict__ resid,
            float* __restrict__ C,
            int M, int N, int K, float alpha,
            long long sA, long long sB, long long sC)
{
    __shared__ float As[2][BK][BM];
    __shared__ float Bs[2][BK][BN];

    const int tid = threadIdx.x;
    const long long bz = blockIdx.z;
    A  += bz * sA;
    Bm += bz * sB;
    C  += bz * sC;

    const int bm = blockIdx.y * BM;
    const int bn = blockIdx.x * BN;

    // A-tile (and NT B-tile) load mapping: 64 rows x 16 cols per pass, 2 passes
    const int lr = tid >> 2;            // 0..63
    const int lc = (tid & 3) << 2;      // 0,4,8,12 (k offset)
    // NN B-tile load mapping: 8 rows x 128 cols per pass, 2 passes
    const int br = tid >> 5;            // 0..7
    const int bc = (tid & 31) << 2;     // 0..124

    // 8x8 per-thread output tile
    const int tm = (tid >> 4) << 3;     // 0..120
    const int tn = (tid & 15) << 3;     // 0..120

    float4 pa[2], pb[2];
    float acc[8][8] = {};

    auto fetch = [&](int k0) {
        #pragma unroll
        for (int p = 0; p < 2; p++)
            pa[p] = *reinterpret_cast<const float4*>(
                A + (long long)(bm + lr + p * 64) * K + k0 + lc);
        if (TRANSB) {
            #pragma unroll
            for (int p = 0; p < 2; p++)
                pb[p] = *reinterpret_cast<const float4*>(
                    Bm + (long long)(bn + lr + p * 64) * K + k0 + lc);
        } else {
            #pragma unroll
            for (int p = 0; p < 2; p++)
                pb[p] = *reinterpret_cast<const float4*>(
                    Bm + (long long)(k0 + br + p * 8) * N + bn + bc);
        }
    };

    auto store = [&](int buf) {
        #pragma unroll
        for (int p = 0; p < 2; p++) {
            As[buf][lc + 0][lr + p * 64] = pa[p].x;
            As[buf][lc + 1][lr + p * 64] = pa[p].y;
            As[buf][lc + 2][lr + p * 64] = pa[p].z;
            As[buf][lc + 3][lr + p * 64] = pa[p].w;
        }
        if (TRANSB) {
            #pragma unroll
            for (int p = 0; p < 2; p++) {
                Bs[buf][lc + 0][lr + p * 64] = pb[p].x;
                Bs[buf][lc + 1][lr + p * 64] = pb[p].y;
                Bs[buf][lc + 2][lr + p * 64] = pb[p].z;
                Bs[buf][lc + 3][lr + p * 64] = pb[p].w;
            }
        } else {
            #pragma unroll
            for (int p = 0; p < 2; p++)
                *reinterpret_cast<float4*>(&Bs[buf][br + p * 8][bc]) = pb[p];
        }
    };

    fetch(0);
    store(0);
    __syncthreads();

    const int nk = K / BK;
    for (int kt = 0; kt < nk; kt++) {
        const int cur = kt & 1;
        if (kt + 1 < nk) fetch((kt + 1) * BK);

        #pragma unroll
        for (int k = 0; k < BK; k++) {
            float a0[8], b0[8];
            #pragma unroll
            for (int i = 0; i < 8; i++) a0[i] = As[cur][k][tm + i];
            #pragma unroll
            for (int j = 0; j < 8; j++) b0[j] = Bs[cur][k][tn + j];
            #pragma unroll
            for (int i = 0; i < 8; i++)
                #pragma unroll
                for (int j = 0; j < 8; j++)
                    acc[i][j] = fmaf(a0[i], b0[j], acc[i][j]);
        }

        if (kt + 1 < nk) store(cur ^ 1);
        __syncthreads();
    }

    // Epilogue
    #pragma unroll
    for (int i = 0; i < 8; i++) {
        const long long m = bm + tm + i;
        const long long base = m * N + bn + tn;
        #pragma unroll
        for (int j0 = 0; j0 < 8; j0 += 4) {
            float r[4];
            #pragma unroll
            for (int j = 0; j < 4; j++) r[j] = acc[i][j0 + j] * alpha;
            if (bias) {
                #pragma unroll
                for (int j = 0; j < 4; j++) r[j] += bias[bn + tn + j0 + j];
            }
            if (resid) {
                float4 rv = *reinterpret_cast<const float4*>(resid + base + j0);
                r[0] += rv.x; r[1] += rv.y; r[2] += rv.z; r[3] += rv.w;
            }
            if (ACT == 1) {
                #pragma unroll
                for (int j = 0; j < 4; j++)
                    r[j] = 0.5f * r[j] * (1.0f + erff(r[j] * 0.70710678118654752f));
            }
            float4 o; o.x = r[0]; o.y = r[1]; o.z = r[2]; o.w = r[3];
            *reinterpret_cast<float4*>(C + base + j0) = o;
        }
    }
}

// ---------------- block reductions ---------------------------------------------
__device__ __forceinline__ float block_sum(float v, float* sh)
{
    const int lane = threadIdx.x & 31, w = threadIdx.x >> 5;
    #pragma unroll
    for (int o = 16; o; o >>= 1) v += __shfl_xor_sync(0xffffffffu, v, o);
    __syncthreads();                 // protect sh reuse across calls
    if (lane == 0) sh[w] = v;
    __syncthreads();
    float s = 0.f;
    #pragma unroll
    for (int i = 0; i < 8; i++) s += sh[i];
    return s;
}

__device__ __forceinline__ float block_max(float v, float* sh)
{
    const int lane = threadIdx.x & 31, w = threadIdx.x >> 5;
    #pragma unroll
    for (int o = 16; o; o >>= 1) v = fmaxf(v, __shfl_xor_sync(0xffffffffu, v, o));
    __syncthreads();
    if (lane == 0) sh[w] = v;
    __syncthreads();
    float s = -INFINITY;
    #pragma unroll
    for (int i = 0; i < 8; i++) s = fmaxf(s, sh[i]);
    return s;
}

// ---------------- softmax over rows of length 1024 (in place) -------------------
__global__ void __launch_bounds__(256) softmax_kernel(float* __restrict__ data)
{
    __shared__ float sh[8];
    const long long row = blockIdx.x;
    float4* p = reinterpret_cast<float4*>(data + row * 1024);
    float4 x = p[threadIdx.x];

    float m = fmaxf(fmaxf(x.x, x.y), fmaxf(x.z, x.w));
    m = block_max(m, sh);

    x.x = expf(x.x - m); x.y = expf(x.y - m);
    x.z = expf(x.z - m); x.w = expf(x.w - m);

    float s = x.x + x.y + x.z + x.w;
    s = block_sum(s, sh);
    const float inv = 1.0f / s;

    x.x *= inv; x.y *= inv; x.z *= inv; x.w *= inv;
    p[threadIdx.x] = x;
}

// ---------------- LayerNorm over rows of length 1024 ----------------------------
__global__ void __launch_bounds__(256)
ln_kernel(const float* __restrict__ in, const float* __restrict__ g,
          const float* __restrict__ b, float* __restrict__ out)
{
    __shared__ float sh[8];
    const long long row = blockIdx.x;
    const float4* p = reinterpret_cast<const float4*>(in + row * 1024);
    float4 x = p[threadIdx.x];

    float s = x.x + x.y + x.z + x.w;
    s = block_sum(s, sh);
    const float mu = s * (1.0f / 1024.0f);

    const float dx = x.x - mu, dy = x.y - mu, dz = x.z - mu, dw = x.w - mu;
    float ss = dx * dx + dy * dy + dz * dz + dw * dw;
    ss = block_sum(ss, sh);
    const float rstd = rsqrtf(ss * (1.0f / 1024.0f) + 1e-12f);

    const float4 gg = reinterpret_cast<const float4*>(g)[threadIdx.x];
    const float4 bb = reinterpret_cast<const float4*>(b)[threadIdx.x];

    float4 o;
    o.x = dx * rstd * gg.x + bb.x;
    o.y = dy * rstd * gg.y + bb.y;
    o.z = dz * rstd * gg.z + bb.z;
    o.w = dw * rstd * gg.w + bb.w;
    reinterpret_cast<float4*>(out + row * 1024)[threadIdx.x] = o;
}

// ---------------- host launcher --------------------------------------------------
extern "C" void kernel_launch(void* const* d_in, const int* in_sizes, int n_in,
                              void* d_out, int out_size)
{
    const float* x  = (const float*)d_in[0];
    const float* Wq = (const float*)d_in[1];
    const float* bq = (const float*)d_in[2];
    const float* Wk = (const float*)d_in[3];
    const float* bk = (const float*)d_in[4];
    const float* Wv = (const float*)d_in[5];
    const float* bv = (const float*)d_in[6];
    const float* Wd = (const float*)d_in[7];
    const float* bd = (const float*)d_in[8];
    const float* g1 = (const float*)d_in[9];
    const float* b1 = (const float*)d_in[10];
    const float* Wi = (const float*)d_in[11];
    const float* bi = (const float*)d_in[12];
    const float* Wo = (const float*)d_in[13];
    const float* bo = (const float*)d_in[14];
    const float* g2 = (const float*)d_in[15];
    const float* b2 = (const float*)d_in[16];
    float* out = (float*)d_out;

    float *q, *k, *v, *at, *ao, *tmp, *h1, *ff;
    cudaGetSymbolAddress((void**)&q,   g_q);
    cudaGetSymbolAddress((void**)&k,   g_k);
    cudaGetSymbolAddress((void**)&v,   g_v);
    cudaGetSymbolAddress((void**)&at,  g_at);
    cudaGetSymbolAddress((void**)&ao,  g_ao);
    cudaGetSymbolAddress((void**)&tmp, g_tmp);
    cudaGetSymbolAddress((void**)&h1,  g_h1);
    cudaGetSymbolAddress((void**)&ff,  g_ff);

    const dim3 t(256);
    const long long SE = (long long)Sd * Ed;
    const long long SS = (long long)Sd * Sd;

    // 1) Q, K, V projections: [8192,1024] @ [1024,1024] + bias
    {
        dim3 gr(Ed / BN, MTOT / BM, 1);
        gemm_kernel<false, 0><<<gr, t>>>(x, Wq, bq, nullptr, q, MTOT, Ed, Ed, 1.0f, 0, 0, 0);
        gemm_kernel<false, 0><<<gr, t>>>(x, Wk, bk, nullptr, k, MTOT, Ed, Ed, 1.0f, 0, 0, 0);
        gemm_kernel<false, 0><<<gr, t>>>(x, Wv, bv, nullptr, v, MTOT, Ed, Ed, 1.0f, 0, 0, 0);
    }

    // 2) scores = q @ k^T / sqrt(E)   (batched over B)
    {
        dim3 gr(Sd / BN, Sd / BM, Bd);
        gemm_kernel<true, 0><<<gr, t>>>(q, k, nullptr, nullptr, at,
                                        Sd, Sd, Ed, 0.03125f, SE, SE, SS);
    }

    // 3) softmax rows (in place)
    softmax_kernel<<<Bd * Sd, t>>>(at);

    // 4) attn_out = attn_w @ v   (batched)
    {
        dim3 gr(Ed / BN, Sd / BM, Bd);
        gemm_kernel<false, 0><<<gr, t>>>(at, v, nullptr, nullptr, ao,
                                         Sd, Ed, Sd, 1.0f, SS, SE, SE);
    }

    // 5) tmp = attn_out @ Wd + bd + x ; h1 = LN(tmp)*g1+b1
    {
        dim3 gr(Ed / BN, MTOT / BM, 1);
        gemm_kernel<false, 0><<<gr, t>>>(ao, Wd, bd, x, tmp, MTOT, Ed, Ed, 1.0f, 0, 0, 0);
        ln_kernel<<<MTOT, t>>>(tmp, g1, b1, h1);
    }

    // 6) ff = gelu(h1 @ Wi + bi)
    {
        dim3 gr(Fd / BN, MTOT / BM, 1);
        gemm_kernel<false, 1><<<gr, t>>>(h1, Wi, bi, nullptr, ff, MTOT, Fd, Ed, 1.0f, 0, 0, 0);
    }

    // 7) tmp = ff @ Wo + bo + h1 ; out = LN(tmp)*g2+b2
    {
        dim3 gr(Ed / BN, MTOT / BM, 1);
        gemm_kernel<false, 0><<<gr, t>>>(ff, Wo, bo, h1, tmp, MTOT, Ed, Fd, 1.0f, 0, 0, 0);
        ln_kernel<<<MTOT, t>>>(tmp, g2, b2, out);
    }
}

// round 3
// speedup vs baseline: 3.6987x; 3.6987x over previous
#include <cuda_runtime.h>
#include <math.h>
#include <stdint.h>

// tcgen05 is an architecture-specific feature: only emit it in the sm_103a/sm_100a
// compilation passes. Non-'a' passes (e.g. compute_103) get an empty stub body;
// at runtime the GB300 loads the exact-match sm_103a cubin.
#if defined(__CUDA_ARCH_FEAT_SM103_ALL) || defined(__CUDA_ARCH_FEAT_SM100_ALL) || defined(__CUDA_ARCH_FEAT_SM101_ALL) || defined(__CUDA_ARCH_FEAT_SM110_ALL)
#define HAS_TC 1
#else
#define HAS_TC 0
#endif

// Problem dims
constexpr int Bd = 8;
constexpr int Sd = 1024;
constexpr int Ed = 1024;
constexpr int Fd = 4096;
constexpr int MTOT = Bd * Sd;   // 8192

// tcgen05 GEMM tile config
constexpr int TM = 128;         // M per CTA (M_atom 128, cta_group::1)
constexpr int TN = 256;         // N per CTA (TMEM D cols)
constexpr int TK = 32;          // K elements per stage (= 128B row = 1 SW128 atom col)
constexpr int NS = 4;           // pipeline stages
constexpr int STAGE_BYTES = (TM + TN) * 128;            // 49152
constexpr int SMEM_TOTAL = 1024 + NS * STAGE_BYTES;     // 197632

// idesc: c=F32(1), a=TF32(2), b=TF32(2), K-major both, N=256, M=128
constexpr uint32_t IDESC =
    (1u << 4) | (2u << 7) | (2u << 10) | ((TN / 8) << 17) | ((TM / 16) << 24);

// smem offsets (before tiles)
#define OFF_TMEM   0
#define OFF_FULL(s)  (8 + 8*(s))
#define OFF_EMPTY(s) (8 + 8*NS + 8*(s))
#define OFF_FIN      (8 + 16*NS)

// ---------------- scratch (device globals) ---------------------------------
__device__ float g_xr [(long long)MTOT * Ed];
__device__ float g_q  [(long long)MTOT * Ed];
__device__ float g_k  [(long long)MTOT * Ed];
__device__ float g_v  [(long long)MTOT * Ed];
__device__ float g_vt [(long long)MTOT * Ed];
__device__ float g_at [(long long)Bd * Sd * Sd];
__device__ float g_ao [(long long)MTOT * Ed];
__device__ float g_tmp[(long long)MTOT * Ed];
__device__ float g_h1 [(long long)MTOT * Ed];
__device__ float g_ff [(long long)MTOT * Fd];
__device__ float g_wqt[(long long)Ed * Ed];
__device__ float g_wkt[(long long)Ed * Ed];
__device__ float g_wvt[(long long)Ed * Ed];
__device__ float g_wdt[(long long)Ed * Ed];
__device__ float g_wit[(long long)Fd * Ed];
__device__ float g_wot[(long long)Ed * Fd];

// ---------------- PTX helpers (sm_90-legal ones unguarded) -------------------
__device__ __forceinline__ uint32_t smem_u32(const void* p) {
    uint32_t a;
    asm("{ .reg .u64 t; cvta.to.shared.u64 t, %1; cvt.u32.u64 %0, t; }" : "=r"(a) : "l"(p));
    return a;
}
__device__ __forceinline__ uint32_t elect_one() {
    uint32_t p;
    asm volatile("{ .reg .pred p; elect.sync _|p, 0xFFFFFFFF; selp.b32 %0,1,0,p; }" : "=r"(p));
    return p;
}
__device__ __forceinline__ void mbar_init(uint32_t a, uint32_t c) {
    asm volatile("mbarrier.init.shared.b64 [%0], %1;" :: "r"(a), "r"(c) : "memory");
}
__device__ __forceinline__ void mbar_arrive(uint32_t a) {
    asm volatile("mbarrier.arrive.shared.b64 _, [%0];" :: "r"(a) : "memory");
}
__device__ __forceinline__ void mbar_wait(uint32_t a, uint32_t ph) {
    uint32_t done;
    asm volatile(
        "{\n\t.reg .pred p;\n\t"
        "mbarrier.try_wait.parity.acquire.cta.shared::cta.b64 p, [%1], %2;\n\t"
        "selp.b32 %0, 1, 0, p;\n\t}"
        : "=r"(done) : "r"(a), "r"(ph) : "memory");
    if (!done) {
        asm volatile(
            "{\n\t.reg .pred P1;\n\t"
            "WL%=:\n\t"
            "mbarrier.try_wait.parity.acquire.cta.shared::cta.b64 P1, [%0], %1, 0x989680;\n\t"
            "@P1 bra.uni WD%=;\n\t"
            "bra.uni WL%=;\n\t"
            "WD%=:\n\t}"
            :: "r"(a), "r"(ph) : "memory");
    }
}
__device__ __forceinline__ void cp16(uint32_t dst, const void* src) {
    asm volatile("cp.async.cg.shared.global [%0], [%1], 16;" :: "r"(dst), "l"(src) : "memory");
}
__device__ __forceinline__ uint64_t make_desc(uint32_t addr) {
    // SW128, version=1 (Blackwell), SBO=64, LBO=1
    return 0x4000404000010000ULL | ((uint64_t)(addr >> 4) & 0x3FFF);
}
__device__ __forceinline__ float rna_tf32(float x) {
    uint32_t u;
    asm("cvt.rna.tf32.f32 %0, %1;" : "=r"(u) : "f"(x));
    return __uint_as_float(u);
}

#if HAS_TC
// ---- tcgen05 wrappers: arch-specific, only in the 'a' pass -------------------
__device__ __forceinline__ void mma_tf32(uint32_t d, uint64_t ad, uint64_t bd,
                                         uint32_t idesc, uint32_t en) {
    asm volatile(
        "{\n\t.reg .pred p;\n\t"
        "setp.ne.u32 p, %4, 0;\n\t"
        "tcgen05.mma.cta_group::1.kind::tf32 [%0], %1, %2, %3, {%5, %5, %5, %5}, p;\n\t}"
        :: "r"(d), "l"(ad), "l"(bd), "r"(idesc), "r"(en), "r"(0u)
        : "memory");
}
#define TC_ALLOC(sa, n)   asm volatile("tcgen05.alloc.cta_group::1.sync.aligned.shared::cta.b32 [%0], %1;" :: "r"(sa), "r"(n) : "memory")
#define TC_DEALLOC(t, n)  asm volatile("tcgen05.dealloc.cta_group::1.sync.aligned.b32 %0, %1;" :: "r"(t), "r"(n))
#define TC_RELINQ()       asm volatile("tcgen05.relinquish_alloc_permit.cta_group::1.sync.aligned;")
#define TC_COMMIT(mb)     asm volatile("tcgen05.commit.cta_group::1.mbarrier::arrive::one.shared::cluster.b64 [%0];" :: "r"(mb) : "memory")
#define TC_FENCE_AFTER()  asm volatile("tcgen05.fence::after_thread_sync;" ::: "memory")
#define TC_WAIT_LD()      asm volatile("tcgen05.wait::ld.sync.aligned;" ::: "memory")

#define LDTM_X32(r, ta) \
    asm volatile( \
        "tcgen05.ld.sync.aligned.32x32b.x32.b32 " \
        "{%0, %1, %2, %3, %4, %5, %6, %7, " \
        " %8, %9, %10, %11, %12, %13, %14, %15, " \
        " %16, %17, %18, %19, %20, %21, %22, %23, " \
        " %24, %25, %26, %27, %28, %29, %30, %31}, [%32];" \
        : "=r"((r)[0]),  "=r"((r)[1]),  "=r"((r)[2]),  "=r"((r)[3]), \
          "=r"((r)[4]),  "=r"((r)[5]),  "=r"((r)[6]),  "=r"((r)[7]), \
          "=r"((r)[8]),  "=r"((r)[9]),  "=r"((r)[10]), "=r"((r)[11]), \
          "=r"((r)[12]), "=r"((r)[13]), "=r"((r)[14]), "=r"((r)[15]), \
          "=r"((r)[16]), "=r"((r)[17]), "=r"((r)[18]), "=r"((r)[19]), \
          "=r"((r)[20]), "=r"((r)[21]), "=r"((r)[22]), "=r"((r)[23]), \
          "=r"((r)[24]), "=r"((r)[25]), "=r"((r)[26]), "=r"((r)[27]), \
          "=r"((r)[28]), "=r"((r)[29]), "=r"((r)[30]), "=r"((r)[31]) \
        : "r"(ta))
#endif // HAS_TC

// ---------------- tcgen05 TF32 GEMM ------------------------------------------
// C = act(alpha * A @ Bt^T + bias + resid), A [M,K] K-major, Bt [N,K] K-major.
// ACT: 0=none, 1=exact GELU.  ROUND: RNA-round result to tf32 before store.
template<int ACT, bool ROUND>
__global__ void __launch_bounds__(160, 1)
tc_gemm(const float* __restrict__ A, const float* __restrict__ Bt,
        const float* __restrict__ bias, const float* __restrict__ resid,
        float* __restrict__ C, int K, int N, float alpha,
        long long sA, long long sB, long long sC)
{
#if HAS_TC
    extern __shared__ char smem[];
    const uint32_t sb = smem_u32(smem);
    const int tid = threadIdx.x;
    const int wid = tid >> 5;

    A  += blockIdx.z * sA;
    Bt += blockIdx.z * sB;
    C  += blockIdx.z * sC;
    const int bm = blockIdx.y * TM;
    const int bn = blockIdx.x * TN;
    const int nk = K / TK;

    if (tid == 0) {
        for (int s = 0; s < NS; s++) {
            mbar_init(sb + OFF_FULL(s), 128);
            mbar_init(sb + OFF_EMPTY(s), 1);
        }
        mbar_init(sb + OFF_FIN, 1);
    }
    if (wid == 4) {
        TC_ALLOC(sb + OFF_TMEM, 256);
        TC_RELINQ();
    }
    __syncthreads();
    uint32_t tmem;
    asm volatile("ld.shared.b32 %0, [%1];" : "=r"(tmem) : "r"(sb + OFF_TMEM));

    if (tid < 128) {
        // ---- producer: cp.async K-chunks into swizzled stages ----
        const float* aRow  = A  + (long long)(bm + tid) * K;
        const float* bRow0 = Bt + (long long)(bn + tid) * K;
        const float* bRow1 = bRow0 + 128LL * K;
        uint32_t offA[8], offB1[8];
        #pragma unroll
        for (int c = 0; c < 8; c++) {
            uint32_t oa = tid * 128 + c * 16;
            offA[c] = oa ^ ((oa >> 3) & 0x70);
            uint32_t ob = (tid + 128) * 128 + c * 16;
            offB1[c] = ob ^ ((ob >> 3) & 0x70);
        }

        int s = 0; uint32_t eph = 1;
        for (int kt = 0; kt < nk; kt++) {
            mbar_wait(sb + OFF_EMPTY(s), eph);
            const uint32_t stA = sb + 1024 + s * STAGE_BYTES;
            const uint32_t stB = stA + TM * 128;
            const float* a  = aRow  + kt * TK;
            const float* b0 = bRow0 + kt * TK;
            const float* b1 = bRow1 + kt * TK;
            #pragma unroll
            for (int c = 0; c < 8; c++) cp16(stA + offA[c],  a  + c * 4);
            #pragma unroll
            for (int c = 0; c < 8; c++) cp16(stB + offA[c],  b0 + c * 4);
            #pragma unroll
            for (int c = 0; c < 8; c++) cp16(stB + offB1[c], b1 + c * 4);
            asm volatile("cp.async.commit_group;" ::: "memory");
            if (kt >= NS - 1) {
                asm volatile("cp.async.wait_group %0;" :: "n"(NS - 1) : "memory");
                asm volatile("fence.proxy.async.shared::cta;" ::: "memory");
                mbar_arrive(sb + OFF_FULL((kt - (NS - 1)) % NS));
            }
            if (++s == NS) { s = 0; eph ^= 1; }
        }
        asm volatile("cp.async.wait_group 0;" ::: "memory");
        asm volatile("fence.proxy.async.shared::cta;" ::: "memory");
        for (int j = nk - (NS - 1); j < nk; j++)
            mbar_arrive(sb + OFF_FULL(j % NS));

        // ---- epilogue: read TMEM, fuse bias/resid/act, store ----
        mbar_wait(sb + OFF_FIN, 0);
        TC_FENCE_AFTER();
        const int lane = tid & 31;
        const long long row = bm + (tid >> 5) * 32 + lane;
        float* crow = C + row * (long long)N + bn;
        const float* rrow = resid ? resid + row * (long long)N + bn : nullptr;

        #pragma unroll 1
        for (int c = 0; c < 8; c++) {
            uint32_t r[32];
            LDTM_X32(r, tmem + c * 32);
            TC_WAIT_LD();
            float v[32];
            #pragma unroll
            for (int j = 0; j < 32; j++) v[j] = __uint_as_float(r[j]) * alpha;
            if (bias) {
                #pragma unroll
                for (int j0 = 0; j0 < 32; j0 += 4) {
                    float4 bb = *reinterpret_cast<const float4*>(bias + bn + c * 32 + j0);
                    v[j0+0] += bb.x; v[j0+1] += bb.y; v[j0+2] += bb.z; v[j0+3] += bb.w;
                }
            }
            if (rrow) {
                #pragma unroll
                for (int j0 = 0; j0 < 32; j0 += 4) {
                    float4 rv = *reinterpret_cast<const float4*>(rrow + c * 32 + j0);
                    v[j0+0] += rv.x; v[j0+1] += rv.y; v[j0+2] += rv.z; v[j0+3] += rv.w;
                }
            }
            if constexpr (ACT == 1) {
                #pragma unroll
                for (int j = 0; j < 32; j++)
                    v[j] = 0.5f * v[j] * (1.0f + erff(v[j] * 0.70710678118654752f));
            }
            if constexpr (ROUND) {
                #pragma unroll
                for (int j = 0; j < 32; j++) v[j] = rna_tf32(v[j]);
            }
            #pragma unroll
            for (int j0 = 0; j0 < 32; j0 += 4) {
                float4 o; o.x = v[j0]; o.y = v[j0+1]; o.z = v[j0+2]; o.w = v[j0+3];
                *reinterpret_cast<float4*>(crow + c * 32 + j0) = o;
            }
        }
    } else {
        // ---- warp 4: MMA issuer ----
        uint32_t ep = elect_one();
        int s = 0; uint32_t ph = 0;
        for (int kt = 0; kt < nk; kt++) {
            mbar_wait(sb + OFF_FULL(s), ph);
            if (ep) {
                const uint32_t stA = sb + 1024 + s * STAGE_BYTES;
                uint64_t ad = make_desc(stA);
                uint64_t bd = make_desc(stA + TM * 128);
                #pragma unroll
                for (int j = 0; j < 4; j++)
                    mma_tf32(tmem, ad + 2 * j, bd + 2 * j, IDESC, (uint32_t)((kt | j) != 0));
                if (kt == nk - 1) TC_COMMIT(sb + OFF_FIN);
                else              TC_COMMIT(sb + OFF_EMPTY(s));
            }
            if (++s == NS) { s = 0; ph ^= 1; }
        }
    }

    __syncthreads();
    if (wid == 4) TC_DEALLOC(tmem, 256);
#endif // HAS_TC
}

// ---------------- elementwise kernels ---------------------------------------
__device__ __forceinline__ float block_sum(float v, float* sh) {
    const int lane = threadIdx.x & 31, w = threadIdx.x >> 5;
    #pragma unroll
    for (int o = 16; o; o >>= 1) v += __shfl_xor_sync(0xffffffffu, v, o);
    __syncthreads();
    if (lane == 0) sh[w] = v;
    __syncthreads();
    float s = 0.f;
    #pragma unroll
    for (int i = 0; i < 8; i++) s += sh[i];
    return s;
}
__device__ __forceinline__ float block_max(float v, float* sh) {
    const int lane = threadIdx.x & 31, w = threadIdx.x >> 5;
    #pragma unroll
    for (int o = 16; o; o >>= 1) v = fmaxf(v, __shfl_xor_sync(0xffffffffu, v, o));
    __syncthreads();
    if (lane == 0) sh[w] = v;
    __syncthreads();
    float s = -INFINITY;
    #pragma unroll
    for (int i = 0; i < 8; i++) s = fmaxf(s, sh[i]);
    return s;
}

__global__ void __launch_bounds__(256) softmax_kernel(float* __restrict__ data)
{
    __shared__ float sh[8];
    const long long row = blockIdx.x;
    float4* p = reinterpret_cast<float4*>(data + row * 1024);
    float4 x = p[threadIdx.x];
    float m = fmaxf(fmaxf(x.x, x.y), fmaxf(x.z, x.w));
    m = block_max(m, sh);
    x.x = expf(x.x - m); x.y = expf(x.y - m);
    x.z = expf(x.z - m); x.w = expf(x.w - m);
    float s = x.x + x.y + x.z + x.w;
    s = block_sum(s, sh);
    const float inv = 1.0f / s;
    x.x = rna_tf32(x.x * inv); x.y = rna_tf32(x.y * inv);
    x.z = rna_tf32(x.z * inv); x.w = rna_tf32(x.w * inv);
    p[threadIdx.x] = x;
}

template<bool ROUND>
__global__ void __launch_bounds__(256)
ln_kernel(const float* __restrict__ in, const float* __restrict__ g,
          const float* __restrict__ b, float* __restrict__ out)
{
    __shared__ float sh[8];
    const long long row = blockIdx.x;
    const float4* p = reinterpret_cast<const float4*>(in + row * 1024);
    float4 x = p[threadIdx.x];
    float s = x.x + x.y + x.z + x.w;
    s = block_sum(s, sh);
    const float mu = s * (1.0f / 1024.0f);
    const float dx = x.x - mu, dy = x.y - mu, dz = x.z - mu, dw = x.w - mu;
    float ss = dx * dx + dy * dy + dz * dz + dw * dw;
    ss = block_sum(ss, sh);
    const float rstd = rsqrtf(ss * (1.0f / 1024.0f) + 1e-12f);
    const float4 gg = reinterpret_cast<const float4*>(g)[threadIdx.x];
    const float4 bb = reinterpret_cast<const float4*>(b)[threadIdx.x];
    float4 o;
    o.x = dx * rstd * gg.x + bb.x;
    o.y = dy * rstd * gg.y + bb.y;
    o.z = dz * rstd * gg.z + bb.z;
    o.w = dw * rstd * gg.w + bb.w;
    if (ROUND) { o.x = rna_tf32(o.x); o.y = rna_tf32(o.y); o.z = rna_tf32(o.z); o.w = rna_tf32(o.w); }
    reinterpret_cast<float4*>(out + row * 1024)[threadIdx.x] = o;
}

// out[c, r] = rna(in[r, c]); batched via z
__global__ void __launch_bounds__(256)
transpose_round(const float* __restrict__ in, float* __restrict__ out,
                int R, int C, long long sIn, long long sOut)
{
    __shared__ float t[32][33];
    in  += blockIdx.z * sIn;
    out += blockIdx.z * sOut;
    const int c0 = blockIdx.x * 32, r0 = blockIdx.y * 32;
    const int x = threadIdx.x & 31, y = (threadIdx.x >> 5) * 4;
    #pragma unroll
    for (int i = 0; i < 4; i++)
        t[y + i][x] = in[(long long)(r0 + y + i) * C + c0 + x];
    __syncthreads();
    #pragma unroll
    for (int i = 0; i < 4; i++)
        out[(long long)(c0 + y + i) * R + r0 + x] = rna_tf32(t[x][y + i]);
}

__global__ void __launch_bounds__(256)
round_kernel(const float4* __restrict__ in, float4* __restrict__ out, long long n4)
{
    for (long long i = blockIdx.x * 256LL + threadIdx.x; i < n4; i += gridDim.x * 256LL) {
        float4 v = in[i];
        v.x = rna_tf32(v.x); v.y = rna_tf32(v.y);
        v.z = rna_tf32(v.z); v.w = rna_tf32(v.w);
        out[i] = v;
    }
}

// ---------------- host launcher -----------------------------------------------
extern "C" void kernel_launch(void* const* d_in, const int* in_sizes, int n_in,
                              void* d_out, int out_size)
{
    const float* x  = (const float*)d_in[0];
    const float* Wq = (const float*)d_in[1];
    const float* bq = (const float*)d_in[2];
    const float* Wk = (const float*)d_in[3];
    const float* bk = (const float*)d_in[4];
    const float* Wv = (const float*)d_in[5];
    const float* bv = (const float*)d_in[6];
    const float* Wd = (const float*)d_in[7];
    const float* bd = (const float*)d_in[8];
    const float* g1 = (const float*)d_in[9];
    const float* b1 = (const float*)d_in[10];
    const float* Wi = (const float*)d_in[11];
    const float* bi = (const float*)d_in[12];
    const float* Wo = (const float*)d_in[13];
    const float* bo = (const float*)d_in[14];
    const float* g2 = (const float*)d_in[15];
    const float* b2 = (const float*)d_in[16];
    float* out = (float*)d_out;

    float *xr, *q, *k, *v, *vt, *at, *ao, *tmp, *h1, *ff;
    float *wqt, *wkt, *wvt, *wdt, *wit, *wot;
    cudaGetSymbolAddress((void**)&xr,  g_xr);
    cudaGetSymbolAddress((void**)&q,   g_q);
    cudaGetSymbolAddress((void**)&k,   g_k);
    cudaGetSymbolAddress((void**)&v,   g_v);
    cudaGetSymbolAddress((void**)&vt,  g_vt);
    cudaGetSymbolAddress((void**)&at,  g_at);
    cudaGetSymbolAddress((void**)&ao,  g_ao);
    cudaGetSymbolAddress((void**)&tmp, g_tmp);
    cudaGetSymbolAddress((void**)&h1,  g_h1);
    cudaGetSymbolAddress((void**)&ff,  g_ff);
    cudaGetSymbolAddress((void**)&wqt, g_wqt);
    cudaGetSymbolAddress((void**)&wkt, g_wkt);
    cudaGetSymbolAddress((void**)&wvt, g_wvt);
    cudaGetSymbolAddress((void**)&wdt, g_wdt);
    cudaGetSymbolAddress((void**)&wit, g_wit);
    cudaGetSymbolAddress((void**)&wot, g_wot);

    cudaFuncSetAttribute(tc_gemm<0, true>,  cudaFuncAttributeMaxDynamicSharedMemorySize, SMEM_TOTAL);
    cudaFuncSetAttribute(tc_gemm<0, false>, cudaFuncAttributeMaxDynamicSharedMemorySize, SMEM_TOTAL);
    cudaFuncSetAttribute(tc_gemm<1, true>,  cudaFuncAttributeMaxDynamicSharedMemorySize, SMEM_TOTAL);

    const long long SE = (long long)Sd * Ed;
    const long long SS = (long long)Sd * Sd;
    const dim3 tb(256);
    const dim3 gt(160);

    // 0) round inputs / transpose weights (RNA-rounded)
    round_kernel<<<256, tb>>>((const float4*)x, (float4*)xr, (long long)MTOT * Ed / 4);
    transpose_round<<<dim3(Ed/32, Ed/32, 1), tb>>>(Wq, wqt, Ed, Ed, 0, 0);
    transpose_round<<<dim3(Ed/32, Ed/32, 1), tb>>>(Wk, wkt, Ed, Ed, 0, 0);
    transpose_round<<<dim3(Ed/32, Ed/32, 1), tb>>>(Wv, wvt, Ed, Ed, 0, 0);
    transpose_round<<<dim3(Ed/32, Ed/32, 1), tb>>>(Wd, wdt, Ed, Ed, 0, 0);
    transpose_round<<<dim3(Fd/32, Ed/32, 1), tb>>>(Wi, wit, Ed, Fd, 0, 0);
    transpose_round<<<dim3(Ed/32, Fd/32, 1), tb>>>(Wo, wot, Fd, Ed, 0, 0);

    // 1) Q, K, V projections
    {
        dim3 gr(Ed / TN, MTOT / TM, 1);
        tc_gemm<0, true><<<gr, gt, SMEM_TOTAL>>>(xr, wqt, bq, nullptr, q, Ed, Ed, 1.0f, 0, 0, 0);
        tc_gemm<0, true><<<gr, gt, SMEM_TOTAL>>>(xr, wkt, bk, nullptr, k, Ed, Ed, 1.0f, 0, 0, 0);
        tc_gemm<0, true><<<gr, gt, SMEM_TOTAL>>>(xr, wvt, bv, nullptr, v, Ed, Ed, 1.0f, 0, 0, 0);
    }

    // 2) scores = q @ k^T / 32 (batched; k is already [S,E] K-major)
    {
        dim3 gr(Sd / TN, Sd / TM, Bd);
        tc_gemm<0, false><<<gr, gt, SMEM_TOTAL>>>(q, k, nullptr, nullptr, at, Ed, Sd, 0.03125f, SE, SE, SS);
    }

    // 3) softmax rows (RNA-rounded output)
    softmax_kernel<<<Bd * Sd, tb>>>(at);

    // 4) transpose v -> vt (batched), then attn_out = attn_w @ v
    transpose_round<<<dim3(Ed/32, Sd/32, Bd), tb>>>(v, vt, Sd, Ed, SE, SE);
    {
        dim3 gr(Ed / TN, Sd / TM, Bd);
        tc_gemm<0, true><<<gr, gt, SMEM_TOTAL>>>(at, vt, nullptr, nullptr, ao, Sd, Ed, 1.0f, SS, SE, SE);
    }

    // 5) tmp = ao @ Wd + bd + x ; h1 = LN(tmp) (rounded)
    {
        dim3 gr(Ed / TN, MTOT / TM, 1);
        tc_gemm<0, false><<<gr, gt, SMEM_TOTAL>>>(ao, wdt, bd, x, tmp, Ed, Ed, 1.0f, 0, 0, 0);
        ln_kernel<true><<<MTOT, tb>>>(tmp, g1, b1, h1);
    }

    // 6) ff = gelu(h1 @ Wi + bi) (rounded)
    {
        dim3 gr(Fd / TN, MTOT / TM, 1);
        tc_gemm<1, true><<<gr, gt, SMEM_TOTAL>>>(h1, wit, bi, nullptr, ff, Ed, Fd, 1.0f, 0, 0, 0);
    }

    // 7) tmp = ff @ Wo + bo + h1 ; out = LN(tmp) (exact)
    {
        dim3 gr(Ed / TN, MTOT / TM, 1);
        tc_gemm<0, false><<<gr, gt, SMEM_TOTAL>>>(ff, wot, bo, h1, tmp, Fd, Ed, 1.0f, 0, 0, 0);
        ln_kernel<false><<<MTOT, tb>>>(tmp, g2, b2, out);
    }
}

// round 5
// speedup vs baseline: 9.0049x; 2.4346x over previous
#include <cuda_runtime.h>
#include <math.h>
#include <stdint.h>

// tcgen05 is an architecture-specific feature: only emit it in the sm_103a/sm_100a
// compilation passes. Non-'a' passes get an empty stub body.
#if defined(__CUDA_ARCH_FEAT_SM103_ALL) || defined(__CUDA_ARCH_FEAT_SM100_ALL) || defined(__CUDA_ARCH_FEAT_SM101_ALL) || defined(__CUDA_ARCH_FEAT_SM110_ALL)
#define HAS_TC 1
#else
#define HAS_TC 0
#endif

// Problem dims
constexpr int Bd = 8;
constexpr int Sd = 1024;
constexpr int Ed = 1024;
constexpr int Fd = 4096;
constexpr int MTOT = Bd * Sd;   // 8192

// tcgen05 GEMM tile config
constexpr int TM = 128;
constexpr int TN = 256;
constexpr int TK = 32;          // K elems per stage (128B per row)
constexpr int NS = 4;           // pipeline stages
constexpr int STAGE_BYTES = (TM + TN) * 128;            // 49152
constexpr int SMEM_TOTAL = 1024 + NS * STAGE_BYTES;     // 197632

// idesc: c=F32(1), a=TF32(2), b=TF32(2), K-major both, N=256, M=128
constexpr uint32_t IDESC =
    (1u << 4) | (2u << 7) | (2u << 10) | ((TN / 8) << 17) | ((TM / 16) << 24);

#define OFF_TMEM   0
#define OFF_FULL(s)  (8 + 8*(s))
#define OFF_EMPTY(s) (8 + 8*NS + 8*(s))
#define OFF_FIN      (8 + 16*NS)

// ---------------- scratch (device globals) ---------------------------------
__device__ float g_xr  [(long long)MTOT * Ed];
__device__ float g_qkv [(long long)3 * MTOT * Ed];   // q | k | v contiguous
__device__ float g_vt  [(long long)MTOT * Ed];
__device__ float g_at  [(long long)Bd * Sd * Sd];
__device__ float g_ao  [(long long)MTOT * Ed];
__device__ float g_tmp [(long long)MTOT * Ed];
__device__ float g_h1  [(long long)MTOT * Ed];
__device__ float g_ff  [(long long)MTOT * Fd];
__device__ float g_wqkvt[(long long)3 * Ed * Ed];    // Wq^T | Wk^T | Wv^T
__device__ float g_b3  [3 * Ed];
__device__ float g_wdt [(long long)Ed * Ed];
__device__ float g_wit [(long long)Fd * Ed];
__device__ float g_wot [(long long)Ed * Fd];

// ---------------- PTX helpers -------------------------------------------------
__device__ __forceinline__ uint32_t smem_u32(const void* p) {
    uint32_t a;
    asm("{ .reg .u64 t; cvta.to.shared.u64 t, %1; cvt.u32.u64 %0, t; }" : "=r"(a) : "l"(p));
    return a;
}
__device__ __forceinline__ uint32_t elect_one() {
    uint32_t p;
    asm volatile("{ .reg .pred p; elect.sync _|p, 0xFFFFFFFF; selp.b32 %0,1,0,p; }" : "=r"(p));
    return p;
}
__device__ __forceinline__ void mbar_init(uint32_t a, uint32_t c) {
    asm volatile("mbarrier.init.shared.b64 [%0], %1;" :: "r"(a), "r"(c) : "memory");
}
__device__ __forceinline__ void mbar_arrive(uint32_t a) {
    asm volatile("mbarrier.arrive.shared.b64 _, [%0];" :: "r"(a) : "memory");
}
__device__ __forceinline__ void mbar_wait(uint32_t a, uint32_t ph) {
    uint32_t done;
    asm volatile(
        "{\n\t.reg .pred p;\n\t"
        "mbarrier.try_wait.parity.acquire.cta.shared::cta.b64 p, [%1], %2;\n\t"
        "selp.b32 %0, 1, 0, p;\n\t}"
        : "=r"(done) : "r"(a), "r"(ph) : "memory");
    if (!done) {
        asm volatile(
            "{\n\t.reg .pred P1;\n\t"
            "WL%=:\n\t"
            "mbarrier.try_wait.parity.acquire.cta.shared::cta.b64 P1, [%0], %1, 0x989680;\n\t"
            "@P1 bra.uni WD%=;\n\t"
            "bra.uni WL%=;\n\t"
            "WD%=:\n\t}"
            :: "r"(a), "r"(ph) : "memory");
    }
}
__device__ __forceinline__ void cp16(uint32_t dst, const void* src) {
    asm volatile("cp.async.cg.shared.global [%0], [%1], 16;" :: "r"(dst), "l"(src) : "memory");
}
__device__ __forceinline__ uint64_t make_desc(uint32_t addr) {
    // SW128, version=1 (Blackwell), SBO=64, LBO=1
    return 0x4000404000010000ULL | ((uint64_t)(addr >> 4) & 0x3FFF);
}
__device__ __forceinline__ float rna_tf32(float x) {
    uint32_t u;
    asm("cvt.rna.tf32.f32 %0, %1;" : "=r"(u) : "f"(x));
    return __uint_as_float(u);
}

#if HAS_TC
__device__ __forceinline__ void mma_tf32(uint32_t d, uint64_t ad, uint64_t bd,
                                         uint32_t idesc, uint32_t en) {
    asm volatile(
        "{\n\t.reg .pred p;\n\t"
        "setp.ne.u32 p, %4, 0;\n\t"
        "tcgen05.mma.cta_group::1.kind::tf32 [%0], %1, %2, %3, {%5, %5, %5, %5}, p;\n\t}"
        :: "r"(d), "l"(ad), "l"(bd), "r"(idesc), "r"(en), "r"(0u)
        : "memory");
}
#define TC_ALLOC(sa, n)   asm volatile("tcgen05.alloc.cta_group::1.sync.aligned.shared::cta.b32 [%0], %1;" :: "r"(sa), "r"(n) : "memory")
#define TC_DEALLOC(t, n)  asm volatile("tcgen05.dealloc.cta_group::1.sync.aligned.b32 %0, %1;" :: "r"(t), "r"(n))
#define TC_RELINQ()       asm volatile("tcgen05.relinquish_alloc_permit.cta_group::1.sync.aligned;")
#define TC_COMMIT(mb)     asm volatile("tcgen05.commit.cta_group::1.mbarrier::arrive::one.shared::cluster.b64 [%0];" :: "r"(mb) : "memory")
#define TC_FENCE_AFTER()  asm volatile("tcgen05.fence::after_thread_sync;" ::: "memory")
#define TC_WAIT_LD()      asm volatile("tcgen05.wait::ld.sync.aligned;" ::: "memory")

#define LDTM_X32(r, ta) \
    asm volatile( \
        "tcgen05.ld.sync.aligned.32x32b.x32.b32 " \
        "{%0, %1, %2, %3, %4, %5, %6, %7, " \
        " %8, %9, %10, %11, %12, %13, %14, %15, " \
        " %16, %17, %18, %19, %20, %21, %22, %23, " \
        " %24, %25, %26, %27, %28, %29, %30, %31}, [%32];" \
        : "=r"((r)[0]),  "=r"((r)[1]),  "=r"((r)[2]),  "=r"((r)[3]), \
          "=r"((r)[4]),  "=r"((r)[5]),  "=r"((r)[6]),  "=r"((r)[7]), \
          "=r"((r)[8]),  "=r"((r)[9]),  "=r"((r)[10]), "=r"((r)[11]), \
          "=r"((r)[12]), "=r"((r)[13]), "=r"((r)[14]), "=r"((r)[15]), \
          "=r"((r)[16]), "=r"((r)[17]), "=r"((r)[18]), "=r"((r)[19]), \
          "=r"((r)[20]), "=r"((r)[21]), "=r"((r)[22]), "=r"((r)[23]), \
          "=r"((r)[24]), "=r"((r)[25]), "=r"((r)[26]), "=r"((r)[27]), \
          "=r"((r)[28]), "=r"((r)[29]), "=r"((r)[30]), "=r"((r)[31]) \
        : "r"(ta))
#endif // HAS_TC

// ---------------- tcgen05 TF32 GEMM ------------------------------------------
// C = act(alpha * A @ Bt^T + bias + resid), A [M,K] K-major, Bt [N,K] K-major.
// Producer mapping is warp-coalesced: each cp.async instruction's 32 lanes cover
// 4 complete 128B rows (full-sector utilization).
template<int ACT, bool ROUND>
__global__ void __launch_bounds__(160, 1)
tc_gemm(const float* __restrict__ A, const float* __restrict__ Bt,
        const float* __restrict__ bias, const float* __restrict__ resid,
        float* __restrict__ C, int K, int N, float alpha,
        long long sA, long long sB, long long sC, long long sBias)
{
#if HAS_TC
    extern __shared__ char smem[];
    const uint32_t sb = smem_u32(smem);
    const int tid = threadIdx.x;
    const int wid = tid >> 5;

    A    += blockIdx.z * sA;
    Bt   += blockIdx.z * sB;
    C    += blockIdx.z * sC;
    if (bias) bias += blockIdx.z * sBias;
    const int bm = blockIdx.y * TM;
    const int bn = blockIdx.x * TN;
    const int nk = K / TK;

    if (tid == 0) {
        for (int s = 0; s < NS; s++) {
            mbar_init(sb + OFF_FULL(s), 128);
            mbar_init(sb + OFF_EMPTY(s), 1);
        }
        mbar_init(sb + OFF_FIN, 1);
    }
    if (wid == 4) {
        TC_ALLOC(sb + OFF_TMEM, 256);
        TC_RELINQ();
    }
    __syncthreads();
    uint32_t tmem;
    asm volatile("ld.shared.b32 %0, [%1];" : "=r"(tmem) : "r"(sb + OFF_TMEM));

    if (tid < 128) {
        // ---- producer ----
        // a = tid>>3 in 0..15 selects row-phase, c = tid&7 selects 16B chunk.
        // A chunks m=0..7: row a+16m; B chunks m=0..15: row a+16m.
        const int a = tid >> 3;
        const int c = tid & 7;
        const float* pA = A  + (long long)(bm + a) * K + c * 4;
        const float* pB = Bt + (long long)(bn + a) * K + c * 4;
        uint32_t o0 = (uint32_t)(a * 128 + c * 16);
        const uint32_t swA = o0 ^ ((o0 >> 3) & 0x70);       // row bits 0-2 = a&7; same for all m
        const long long strideRow16 = 16LL * K;

        int s = 0; uint32_t eph = 1;
        for (int kt = 0; kt < nk; kt++) {
            mbar_wait(sb + OFF_EMPTY(s), eph);
            const uint32_t st = sb + 1024 + s * STAGE_BYTES;
            #pragma unroll
            for (int m = 0; m < 8; m++)
                cp16(st + swA + m * 2048, pA + m * strideRow16);
            #pragma unroll
            for (int m = 0; m < 16; m++)
                cp16(st + swA + 16384 + m * 2048, pB + m * strideRow16);
            asm volatile("cp.async.commit_group;" ::: "memory");
            pA += TK; pB += TK;
            if (kt >= NS - 1) {
                asm volatile("cp.async.wait_group %0;" :: "n"(NS - 1) : "memory");
                asm volatile("fence.proxy.async.shared::cta;" ::: "memory");
                mbar_arrive(sb + OFF_FULL((kt - (NS - 1)) % NS));
            }
            if (++s == NS) { s = 0; eph ^= 1; }
        }
        asm volatile("cp.async.wait_group 0;" ::: "memory");
        asm volatile("fence.proxy.async.shared::cta;" ::: "memory");
        for (int j = nk - (NS - 1); j < nk; j++)
            mbar_arrive(sb + OFF_FULL(j % NS));

        // ---- epilogue ----
        mbar_wait(sb + OFF_FIN, 0);
        TC_FENCE_AFTER();
        const int lane = tid & 31;
        const long long row = bm + (tid >> 5) * 32 + lane;
        float* crow = C + row * (long long)N + bn;
        const float* rrow = resid ? resid + row * (long long)N + bn : nullptr;

        #pragma unroll 1
        for (int cb = 0; cb < 8; cb++) {
            uint32_t r[32];
            LDTM_X32(r, tmem + cb * 32);
            TC_WAIT_LD();
            float v[32];
            #pragma unroll
            for (int j = 0; j < 32; j++) v[j] = __uint_as_float(r[j]) * alpha;
            if (bias) {
                #pragma unroll
                for (int j0 = 0; j0 < 32; j0 += 4) {
                    float4 bb = *reinterpret_cast<const float4*>(bias + bn + cb * 32 + j0);
                    v[j0+0] += bb.x; v[j0+1] += bb.y; v[j0+2] += bb.z; v[j0+3] += bb.w;
                }
            }
            if (rrow) {
                #pragma unroll
                for (int j0 = 0; j0 < 32; j0 += 4) {
                    float4 rv = *reinterpret_cast<const float4*>(rrow + cb * 32 + j0);
                    v[j0+0] += rv.x; v[j0+1] += rv.y; v[j0+2] += rv.z; v[j0+3] += rv.w;
                }
            }
            if constexpr (ACT == 1) {
                #pragma unroll
                for (int j = 0; j < 32; j++)
                    v[j] = 0.5f * v[j] * (1.0f + erff(v[j] * 0.70710678118654752f));
            }
            if constexpr (ROUND) {
                #pragma unroll
                for (int j = 0; j < 32; j++) v[j] = rna_tf32(v[j]);
            }
            #pragma unroll
            for (int j0 = 0; j0 < 32; j0 += 4) {
                float4 o; o.x = v[j0]; o.y = v[j0+1]; o.z = v[j0+2]; o.w = v[j0+3];
                *reinterpret_cast<float4*>(crow + cb * 32 + j0) = o;
            }
        }
    } else {
        // ---- warp 4: MMA issuer ----
        uint32_t ep = elect_one();
        int s = 0; uint32_t ph = 0;
        for (int kt = 0; kt < nk; kt++) {
            mbar_wait(sb + OFF_FULL(s), ph);
            if (ep) {
                const uint32_t st = sb + 1024 + s * STAGE_BYTES;
                uint64_t ad = make_desc(st);
                uint64_t bd = make_desc(st + TM * 128);
                #pragma unroll
                for (int j = 0; j < 4; j++)
                    mma_tf32(tmem, ad + 2 * j, bd + 2 * j, IDESC, (uint32_t)((kt | j) != 0));
                if (kt == nk - 1) TC_COMMIT(sb + OFF_FIN);
                else              TC_COMMIT(sb + OFF_EMPTY(s));
            }
            if (++s == NS) { s = 0; ph ^= 1; }
        }
    }

    __syncthreads();
    if (wid == 4) TC_DEALLOC(tmem, 256);
#endif // HAS_TC
}

// ---------------- elementwise kernels ---------------------------------------
__device__ __forceinline__ float block_sum(float v, float* sh) {
    const int lane = threadIdx.x & 31, w = threadIdx.x >> 5;
    #pragma unroll
    for (int o = 16; o; o >>= 1) v += __shfl_xor_sync(0xffffffffu, v, o);
    __syncthreads();
    if (lane == 0) sh[w] = v;
    __syncthreads();
    float s = 0.f;
    #pragma unroll
    for (int i = 0; i < 8; i++) s += sh[i];
    return s;
}
__device__ __forceinline__ float block_max(float v, float* sh) {
    const int lane = threadIdx.x & 31, w = threadIdx.x >> 5;
    #pragma unroll
    for (int o = 16; o; o >>= 1) v = fmaxf(v, __shfl_xor_sync(0xffffffffu, v, o));
    __syncthreads();
    if (lane == 0) sh[w] = v;
    __syncthreads();
    float s = -INFINITY;
    #pragma unroll
    for (int i = 0; i < 8; i++) s = fmaxf(s, sh[i]);
    return s;
}

__global__ void __launch_bounds__(256) softmax_kernel(float* __restrict__ data)
{
    __shared__ float sh[8];
    const long long row = blockIdx.x;
    float4* p = reinterpret_cast<float4*>(data + row * 1024);
    float4 x = p[threadIdx.x];
    float m = fmaxf(fmaxf(x.x, x.y), fmaxf(x.z, x.w));
    m = block_max(m, sh);
    x.x = expf(x.x - m); x.y = expf(x.y - m);
    x.z = expf(x.z - m); x.w = expf(x.w - m);
    float s = x.x + x.y + x.z + x.w;
    s = block_sum(s, sh);
    const float inv = 1.0f / s;
    x.x = rna_tf32(x.x * inv); x.y = rna_tf32(x.y * inv);
    x.z = rna_tf32(x.z * inv); x.w = rna_tf32(x.w * inv);
    p[threadIdx.x] = x;
}

template<bool ROUND>
__global__ void __launch_bounds__(256)
ln_kernel(const float* __restrict__ in, const float* __restrict__ g,
          const float* __restrict__ b, float* __restrict__ out)
{
    __shared__ float sh[8];
    const long long row = blockIdx.x;
    const float4* p = reinterpret_cast<const float4*>(in + row * 1024);
    float4 x = p[threadIdx.x];
    float s = x.x + x.y + x.z + x.w;
    s = block_sum(s, sh);
    const float mu = s * (1.0f / 1024.0f);
    const float dx = x.x - mu, dy = x.y - mu, dz = x.z - mu, dw = x.w - mu;
    float ss = dx * dx + dy * dy + dz * dz + dw * dw;
    ss = block_sum(ss, sh);
    const float rstd = rsqrtf(ss * (1.0f / 1024.0f) + 1e-12f);
    const float4 gg = reinterpret_cast<const float4*>(g)[threadIdx.x];
    const float4 bb = reinterpret_cast<const float4*>(b)[threadIdx.x];
    float4 o;
    o.x = dx * rstd * gg.x + bb.x;
    o.y = dy * rstd * gg.y + bb.y;
    o.z = dz * rstd * gg.z + bb.z;
    o.w = dw * rstd * gg.w + bb.w;
    if (ROUND) { o.x = rna_tf32(o.x); o.y = rna_tf32(o.y); o.z = rna_tf32(o.z); o.w = rna_tf32(o.w); }
    reinterpret_cast<float4*>(out + row * 1024)[threadIdx.x] = o;
}

// Fast 64x64 transpose: out[c, r] = (rna) in[r, c]; batched via z.
// in is [R, C]; launch grid = (C/64, R/64, batch).
template<bool ROUND>
__global__ void __launch_bounds__(256)
transpose_fast(const float* __restrict__ in, float* __restrict__ out,
               int R, int C, long long sIn, long long sOut)
{
    __shared__ float t[64][65];
    in  += blockIdx.z * sIn;
    out += blockIdx.z * sOut;
    const int r0 = blockIdx.y * 64, c0 = blockIdx.x * 64;
    const int fc = (threadIdx.x & 15) * 4;   // 0..60
    const int fr = threadIdx.x >> 4;         // 0..15

    #pragma unroll
    for (int i = 0; i < 4; i++) {
        const int r = fr + i * 16;
        float4 x = *reinterpret_cast<const float4*>(in + (long long)(r0 + r) * C + c0 + fc);
        t[fc + 0][r] = x.x; t[fc + 1][r] = x.y; t[fc + 2][r] = x.z; t[fc + 3][r] = x.w;
    }
    __syncthreads();
    #pragma unroll
    for (int i = 0; i < 4; i++) {
        const int oc = fr + i * 16;          // output row (= input col)
        float4 y;
        y.x = t[oc][fc + 0]; y.y = t[oc][fc + 1];
        y.z = t[oc][fc + 2]; y.w = t[oc][fc + 3];
        if (ROUND) {
            y.x = rna_tf32(y.x); y.y = rna_tf32(y.y);
            y.z = rna_tf32(y.z); y.w = rna_tf32(y.w);
        }
        *reinterpret_cast<float4*>(out + (long long)(c0 + oc) * R + r0 + fc) = y;
    }
}

__global__ void __launch_bounds__(256)
round_kernel(const float4* __restrict__ in, float4* __restrict__ out, long long n4)
{
    for (long long i = blockIdx.x * 256LL + threadIdx.x; i < n4; i += gridDim.x * 256LL) {
        float4 v = in[i];
        v.x = rna_tf32(v.x); v.y = rna_tf32(v.y);
        v.z = rna_tf32(v.z); v.w = rna_tf32(v.w);
        out[i] = v;
    }
}

__global__ void __launch_bounds__(1024)
bias3_kernel(const float* __restrict__ b0, const float* __restrict__ b1,
             const float* __restrict__ b2, float* __restrict__ out)
{
    const float* src = blockIdx.x == 0 ? b0 : (blockIdx.x == 1 ? b1 : b2);
    out[blockIdx.x * 1024 + threadIdx.x] = src[threadIdx.x];
}

// ---------------- host launcher -----------------------------------------------
extern "C" void kernel_launch(void* const* d_in, const int* in_sizes, int n_in,
                              void* d_out, int out_size)
{
    const float* x  = (const float*)d_in[0];
    const float* Wq = (const float*)d_in[1];
    const float* bq = (const float*)d_in[2];
    const float* Wk = (const float*)d_in[3];
    const float* bk = (const float*)d_in[4];
    const float* Wv = (const float*)d_in[5];
    const float* bv = (const float*)d_in[6];
    const float* Wd = (const float*)d_in[7];
    const float* bd = (const float*)d_in[8];
    const float* g1 = (const float*)d_in[9];
    const float* b1 = (const float*)d_in[10];
    const float* Wi = (const float*)d_in[11];
    const float* bi = (const float*)d_in[12];
    const float* Wo = (const float*)d_in[13];
    const float* bo = (const float*)d_in[14];
    const float* g2 = (const float*)d_in[15];
    const float* b2 = (const float*)d_in[16];
    float* out = (float*)d_out;

    float *xr, *qkv, *vt, *at, *ao, *tmp, *h1, *ff;
    float *wqkvt, *b3, *wdt, *wit, *wot;
    cudaGetSymbolAddress((void**)&xr,    g_xr);
    cudaGetSymbolAddress((void**)&qkv,   g_qkv);
    cudaGetSymbolAddress((void**)&vt,    g_vt);
    cudaGetSymbolAddress((void**)&at,    g_at);
    cudaGetSymbolAddress((void**)&ao,    g_ao);
    cudaGetSymbolAddress((void**)&tmp,   g_tmp);
    cudaGetSymbolAddress((void**)&h1,    g_h1);
    cudaGetSymbolAddress((void**)&ff,    g_ff);
    cudaGetSymbolAddress((void**)&wqkvt, g_wqkvt);
    cudaGetSymbolAddress((void**)&b3,    g_b3);
    cudaGetSymbolAddress((void**)&wdt,   g_wdt);
    cudaGetSymbolAddress((void**)&wit,   g_wit);
    cudaGetSymbolAddress((void**)&wot,   g_wot);

    cudaFuncSetAttribute(tc_gemm<0, true>,  cudaFuncAttributeMaxDynamicSharedMemorySize, SMEM_TOTAL);
    cudaFuncSetAttribute(tc_gemm<0, false>, cudaFuncAttributeMaxDynamicSharedMemorySize, SMEM_TOTAL);
    cudaFuncSetAttribute(tc_gemm<1, true>,  cudaFuncAttributeMaxDynamicSharedMemorySize, SMEM_TOTAL);

    const long long ME = (long long)MTOT * Ed;
    const long long SE = (long long)Sd * Ed;
    const long long SS = (long long)Sd * Sd;
    const long long EE = (long long)Ed * Ed;
    float* q = qkv;
    float* k = qkv + ME;
    float* v = qkv + 2 * ME;
    const dim3 tb(256);
    const dim3 gt(160);

    // launches 0-4 (so ncu -s 5 captures the QKV GEMM at launch #5)
    round_kernel<<<256, tb>>>((const float4*)x, (float4*)xr, ME / 4);                       // 0
    transpose_fast<true><<<dim3(Ed/64, Ed/64, 1), tb>>>(Wq, wqkvt,          Ed, Ed, 0, 0);  // 1
    transpose_fast<true><<<dim3(Ed/64, Ed/64, 1), tb>>>(Wk, wqkvt + EE,     Ed, Ed, 0, 0);  // 2
    transpose_fast<true><<<dim3(Ed/64, Ed/64, 1), tb>>>(Wv, wqkvt + 2 * EE, Ed, Ed, 0, 0);  // 3
    bias3_kernel<<<3, 1024>>>(bq, bk, bv, b3);                                              // 4

    // 5: fused QKV projections (grid.z selects weight/bias/output)
    tc_gemm<0, true><<<dim3(Ed/TN, MTOT/TM, 3), gt, SMEM_TOTAL>>>(
        xr, wqkvt, b3, nullptr, qkv, Ed, Ed, 1.0f, 0, EE, ME, Ed);

    // 6: scores = q @ k^T / 32 (batched over B)
    tc_gemm<0, false><<<dim3(Sd/TN, Sd/TM, Bd), gt, SMEM_TOTAL>>>(
        q, k, nullptr, nullptr, at, Ed, Sd, 0.03125f, SE, SE, SS, 0);

    // 7: softmax (RNA-rounded)
    softmax_kernel<<<Bd * Sd, tb>>>(at);

    // 8: v -> vt (batched; v already tf32-rounded by GEMM epilogue). v is [Sd, Ed] per batch.
    transpose_fast<false><<<dim3(Ed/64, Sd/64, Bd), tb>>>(v, vt, Sd, Ed, SE, SE);

    // 9: attn_out = attn_w @ v
    tc_gemm<0, true><<<dim3(Ed/TN, Sd/TM, Bd), gt, SMEM_TOTAL>>>(
        at, vt, nullptr, nullptr, ao, Sd, Ed, 1.0f, SS, SE, SE, 0);

    // 10-12: Wd GEMM (+bias +resid x) then LN1.  Wd is [Ed, Ed].
    transpose_fast<true><<<dim3(Ed/64, Ed/64, 1), tb>>>(Wd, wdt, Ed, Ed, 0, 0);
    tc_gemm<0, false><<<dim3(Ed/TN, MTOT/TM, 1), gt, SMEM_TOTAL>>>(
        ao, wdt, bd, x, tmp, Ed, Ed, 1.0f, 0, 0, 0, 0);
    ln_kernel<true><<<MTOT, tb>>>(tmp, g1, b1, h1);

    // 13-14: ff = gelu(h1 @ Wi + bi).  Wi is [Ed, Fd] -> grid (Fd/64, Ed/64).
    transpose_fast<true><<<dim3(Fd/64, Ed/64, 1), tb>>>(Wi, wit, Ed, Fd, 0, 0);
    tc_gemm<1, true><<<dim3(Fd/TN, MTOT/TM, 1), gt, SMEM_TOTAL>>>(
        h1, wit, bi, nullptr, ff, Ed, Fd, 1.0f, 0, 0, 0, 0);

    // 15-17: out = LN(ff @ Wo + bo + h1).  Wo is [Fd, Ed] -> grid (Ed/64, Fd/64).
    transpose_fast<true><<<dim3(Ed/64, Fd/64, 1), tb>>>(Wo, wot, Fd, Ed, 0, 0);
    tc_gemm<0, false><<<dim3(Ed/TN, MTOT/TM, 1), gt, SMEM_TOTAL>>>(
        ff, wot, bo, h1, tmp, Fd, Ed, 1.0f, 0, 0, 0, 0);
    ln_kernel<false><<<MTOT, tb>>>(tmp, g2, b2, out);
}

// round 6
// speedup vs baseline: 10.3011x; 1.1439x over previous
#include <cuda_runtime.h>
#include <math.h>
#include <stdint.h>

// tcgen05 is an architecture-specific feature: only emit it in the sm_103a/sm_100a
// compilation passes. Non-'a' passes get an empty stub body.
#if defined(__CUDA_ARCH_FEAT_SM103_ALL) || defined(__CUDA_ARCH_FEAT_SM100_ALL) || defined(__CUDA_ARCH_FEAT_SM101_ALL) || defined(__CUDA_ARCH_FEAT_SM110_ALL)
#define HAS_TC 1
#else
#define HAS_TC 0
#endif

// Problem dims
constexpr int Bd = 8;
constexpr int Sd = 1024;
constexpr int Ed = 1024;
constexpr int Fd = 4096;
constexpr int MTOT = Bd * Sd;   // 8192

// tcgen05 GEMM tile config: 256x256 tile = 2 x (128x256) MMA into TMEM halves
constexpr int TMM = 256;        // M per CTA (two 128-row MMA dispatches)
constexpr int TN = 256;         // N per CTA
constexpr int TK = 32;          // K elems per stage (128B per row)
constexpr int NS = 3;           // pipeline stages
constexpr int STAGE_BYTES = (TMM + TN) * 128;           // 65536
constexpr int SMEM_TOTAL = 1024 + NS * STAGE_BYTES;     // 197632

// idesc: c=F32(1), a=TF32(2), b=TF32(2), K-major both, N=256, M=128 (per dispatch)
constexpr uint32_t IDESC =
    (1u << 4) | (2u << 7) | (2u << 10) | ((TN / 8) << 17) | ((128 / 16) << 24);

#define OFF_TMEM   0
#define OFF_FULL(s)  (8 + 8*(s))
#define OFF_EMPTY(s) (8 + 8*NS + 8*(s))
#define OFF_FIN      (8 + 16*NS)

// ---------------- scratch (device globals) ---------------------------------
__device__ float g_xr  [(long long)MTOT * Ed];
__device__ float g_qk  [(long long)2 * MTOT * Ed];   // q | k contiguous
__device__ float g_vt  [(long long)MTOT * Ed];       // V transposed [E,S] per batch
__device__ float g_at  [(long long)Bd * Sd * Sd];
__device__ float g_ao  [(long long)MTOT * Ed];
__device__ float g_tmp [(long long)MTOT * Ed];
__device__ float g_h1  [(long long)MTOT * Ed];
__device__ float g_ff  [(long long)MTOT * Fd];
__device__ float g_wt  [(long long)3 * Ed * Ed];     // Wq^T | Wk^T | Wv^T
__device__ float g_b2  [2 * Ed];
__device__ float g_wdt [(long long)Ed * Ed];
__device__ float g_wit [(long long)Fd * Ed];
__device__ float g_wot [(long long)Ed * Fd];

// ---------------- PTX helpers -------------------------------------------------
__device__ __forceinline__ uint32_t smem_u32(const void* p) {
    uint32_t a;
    asm("{ .reg .u64 t; cvta.to.shared.u64 t, %1; cvt.u32.u64 %0, t; }" : "=r"(a) : "l"(p));
    return a;
}
__device__ __forceinline__ uint32_t elect_one() {
    uint32_t p;
    asm volatile("{ .reg .pred p; elect.sync _|p, 0xFFFFFFFF; selp.b32 %0,1,0,p; }" : "=r"(p));
    return p;
}
__device__ __forceinline__ void mbar_init(uint32_t a, uint32_t c) {
    asm volatile("mbarrier.init.shared.b64 [%0], %1;" :: "r"(a), "r"(c) : "memory");
}
__device__ __forceinline__ void mbar_arrive(uint32_t a) {
    asm volatile("mbarrier.arrive.shared.b64 _, [%0];" :: "r"(a) : "memory");
}
__device__ __forceinline__ void mbar_wait(uint32_t a, uint32_t ph) {
    uint32_t done;
    asm volatile(
        "{\n\t.reg .pred p;\n\t"
        "mbarrier.try_wait.parity.acquire.cta.shared::cta.b64 p, [%1], %2;\n\t"
        "selp.b32 %0, 1, 0, p;\n\t}"
        : "=r"(done) : "r"(a), "r"(ph) : "memory");
    if (!done) {
        asm volatile(
            "{\n\t.reg .pred P1;\n\t"
            "WL%=:\n\t"
            "mbarrier.try_wait.parity.acquire.cta.shared::cta.b64 P1, [%0], %1, 0x989680;\n\t"
            "@P1 bra.uni WD%=;\n\t"
            "bra.uni WL%=;\n\t"
            "WD%=:\n\t}"
            :: "r"(a), "r"(ph) : "memory");
    }
}
__device__ __forceinline__ void cp16(uint32_t dst, const void* src) {
    asm volatile("cp.async.cg.shared.global [%0], [%1], 16;" :: "r"(dst), "l"(src) : "memory");
}
__device__ __forceinline__ uint64_t make_desc(uint32_t addr) {
    // SW128, version=1 (Blackwell), SBO=64, LBO=1
    return 0x4000404000010000ULL | ((uint64_t)(addr >> 4) & 0x3FFF);
}
__device__ __forceinline__ float rna_tf32(float x) {
    uint32_t u;
    asm("cvt.rna.tf32.f32 %0, %1;" : "=r"(u) : "f"(x));
    return __uint_as_float(u);
}

#if HAS_TC
__device__ __forceinline__ void mma_tf32(uint32_t d, uint64_t ad, uint64_t bd,
                                         uint32_t idesc, uint32_t en) {
    asm volatile(
        "{\n\t.reg .pred p;\n\t"
        "setp.ne.u32 p, %4, 0;\n\t"
        "tcgen05.mma.cta_group::1.kind::tf32 [%0], %1, %2, %3, {%5, %5, %5, %5}, p;\n\t}"
        :: "r"(d), "l"(ad), "l"(bd), "r"(idesc), "r"(en), "r"(0u)
        : "memory");
}
#define TC_ALLOC(sa, n)   asm volatile("tcgen05.alloc.cta_group::1.sync.aligned.shared::cta.b32 [%0], %1;" :: "r"(sa), "r"(n) : "memory")
#define TC_DEALLOC(t, n)  asm volatile("tcgen05.dealloc.cta_group::1.sync.aligned.b32 %0, %1;" :: "r"(t), "r"(n))
#define TC_RELINQ()       asm volatile("tcgen05.relinquish_alloc_permit.cta_group::1.sync.aligned;")
#define TC_COMMIT(mb)     asm volatile("tcgen05.commit.cta_group::1.mbarrier::arrive::one.shared::cluster.b64 [%0];" :: "r"(mb) : "memory")
#define TC_FENCE_AFTER()  asm volatile("tcgen05.fence::after_thread_sync;" ::: "memory")
#define TC_WAIT_LD()      asm volatile("tcgen05.wait::ld.sync.aligned;" ::: "memory")

#define LDTM_X32(r, ta) \
    asm volatile( \
        "tcgen05.ld.sync.aligned.32x32b.x32.b32 " \
        "{%0, %1, %2, %3, %4, %5, %6, %7, " \
        " %8, %9, %10, %11, %12, %13, %14, %15, " \
        " %16, %17, %18, %19, %20, %21, %22, %23, " \
        " %24, %25, %26, %27, %28, %29, %30, %31}, [%32];" \
        : "=r"((r)[0]),  "=r"((r)[1]),  "=r"((r)[2]),  "=r"((r)[3]), \
          "=r"((r)[4]),  "=r"((r)[5]),  "=r"((r)[6]),  "=r"((r)[7]), \
          "=r"((r)[8]),  "=r"((r)[9]),  "=r"((r)[10]), "=r"((r)[11]), \
          "=r"((r)[12]), "=r"((r)[13]), "=r"((r)[14]), "=r"((r)[15]), \
          "=r"((r)[16]), "=r"((r)[17]), "=r"((r)[18]), "=r"((r)[19]), \
          "=r"((r)[20]), "=r"((r)[21]), "=r"((r)[22]), "=r"((r)[23]), \
          "=r"((r)[24]), "=r"((r)[25]), "=r"((r)[26]), "=r"((r)[27]), \
          "=r"((r)[28]), "=r"((r)[29]), "=r"((r)[30]), "=r"((r)[31]) \
        : "r"(ta))
#endif // HAS_TC

// ---------------- tcgen05 TF32 GEMM (256x256 tile) -----------------------------
// C = act(alpha * A @ Bt^T + bias + resid), A [M,K] K-major, Bt [N,K] K-major.
// Per stage: A panel 256 rows + B panel 256 rows (64KB). Two M=128 MMA dispatches
// per K-chunk accumulate into TMEM halves D0 (cols 0-255) and D1 (cols 256-511).
// BROW: bias indexed by output ROW (for computing V^T directly); else by column.
template<int ACT, bool ROUND, bool BROW>
__global__ void __launch_bounds__(160, 1)
tc_gemm(const float* __restrict__ A, const float* __restrict__ Bt,
        const float* __restrict__ bias, const float* __restrict__ resid,
        float* __restrict__ C, int K, int N, float alpha,
        long long sA, long long sB, long long sC, long long sBias)
{
#if HAS_TC
    extern __shared__ char smem[];
    const uint32_t sb = smem_u32(smem);
    const int tid = threadIdx.x;
    const int wid = tid >> 5;

    A    += blockIdx.z * sA;
    Bt   += blockIdx.z * sB;
    C    += blockIdx.z * sC;
    if (bias) bias += blockIdx.z * sBias;
    const int bm = blockIdx.y * TMM;
    const int bn = blockIdx.x * TN;
    const int nk = K / TK;

    if (tid == 0) {
        for (int s = 0; s < NS; s++) {
            mbar_init(sb + OFF_FULL(s), 128);
            mbar_init(sb + OFF_EMPTY(s), 1);
        }
        mbar_init(sb + OFF_FIN, 1);
    }
    if (wid == 4) {
        TC_ALLOC(sb + OFF_TMEM, 512);
        TC_RELINQ();
    }
    __syncthreads();
    uint32_t tmem;
    asm volatile("ld.shared.b32 %0, [%1];" : "=r"(tmem) : "r"(sb + OFF_TMEM));

    if (tid < 128) {
        // ---- producer: coalesced cp.async, 32 x 16B per thread per stage ----
        // a = tid>>3 (row phase 0..15), c = tid&7 (16B chunk). Rows a+16m, m=0..15
        // for each of the A (256-row) and B (256-row) panels.
        const int a = tid >> 3;
        const int c = tid & 7;
        const float* pA = A  + (long long)(bm + a) * K + c * 4;
        const float* pB = Bt + (long long)(bn + a) * K + c * 4;
        uint32_t o0 = (uint32_t)(a * 128 + c * 16);
        const uint32_t swA = o0 ^ ((o0 >> 3) & 0x70);   // row bits 0-2 = a&7, invariant in m
        const long long str16 = 16LL * K;

        int s = 0; uint32_t eph = 1;
        for (int kt = 0; kt < nk; kt++) {
            mbar_wait(sb + OFF_EMPTY(s), eph);
            const uint32_t st = sb + 1024 + s * STAGE_BYTES;
            #pragma unroll
            for (int m = 0; m < 16; m++)
                cp16(st + swA + m * 2048, pA + m * str16);
            #pragma unroll
            for (int m = 0; m < 16; m++)
                cp16(st + swA + 32768 + m * 2048, pB + m * str16);
            asm volatile("cp.async.commit_group;" ::: "memory");
            pA += TK; pB += TK;
            if (kt >= NS - 1) {
                asm volatile("cp.async.wait_group %0;" :: "n"(NS - 1) : "memory");
                asm volatile("fence.proxy.async.shared::cta;" ::: "memory");
                mbar_arrive(sb + OFF_FULL((kt - (NS - 1)) % NS));
            }
            if (++s == NS) { s = 0; eph ^= 1; }
        }
        asm volatile("cp.async.wait_group 0;" ::: "memory");
        asm volatile("fence.proxy.async.shared::cta;" ::: "memory");
        for (int j = nk - (NS - 1); j < nk; j++)
            mbar_arrive(sb + OFF_FULL(j % NS));

        // ---- epilogue: both TMEM halves ----
        mbar_wait(sb + OFF_FIN, 0);
        TC_FENCE_AFTER();
        const int lane = tid & 31;

        #pragma unroll 1
        for (int h = 0; h < 2; h++) {
            const long long row = bm + h * 128 + (tid >> 5) * 32 + lane;
            float* crow = C + row * (long long)N + bn;
            const float* rrow = resid ? resid + row * (long long)N + bn : nullptr;
            float brow = 0.0f;
            if (BROW && bias) brow = bias[row];
            const uint32_t tmh = tmem + h * 256;

            #pragma unroll 1
            for (int cb = 0; cb < 8; cb++) {
                uint32_t r[32];
                LDTM_X32(r, tmh + cb * 32);
                TC_WAIT_LD();
                float v[32];
                #pragma unroll
                for (int j = 0; j < 32; j++) v[j] = __uint_as_float(r[j]) * alpha;
                if (bias) {
                    if (BROW) {
                        #pragma unroll
                        for (int j = 0; j < 32; j++) v[j] += brow;
                    } else {
                        #pragma unroll
                        for (int j0 = 0; j0 < 32; j0 += 4) {
                            float4 bb = *reinterpret_cast<const float4*>(bias + bn + cb * 32 + j0);
                            v[j0+0] += bb.x; v[j0+1] += bb.y; v[j0+2] += bb.z; v[j0+3] += bb.w;
                        }
                    }
                }
                if (rrow) {
                    #pragma unroll
                    for (int j0 = 0; j0 < 32; j0 += 4) {
                        float4 rv = *reinterpret_cast<const float4*>(rrow + cb * 32 + j0);
                        v[j0+0] += rv.x; v[j0+1] += rv.y; v[j0+2] += rv.z; v[j0+3] += rv.w;
                    }
                }
                if constexpr (ACT == 1) {
                    #pragma unroll
                    for (int j = 0; j < 32; j++)
                        v[j] = 0.5f * v[j] * (1.0f + erff(v[j] * 0.70710678118654752f));
                }
                if constexpr (ROUND) {
                    #pragma unroll
                    for (int j = 0; j < 32; j++) v[j] = rna_tf32(v[j]);
                }
                #pragma unroll
                for (int j0 = 0; j0 < 32; j0 += 4) {
                    float4 o; o.x = v[j0]; o.y = v[j0+1]; o.z = v[j0+2]; o.w = v[j0+3];
                    *reinterpret_cast<float4*>(crow + cb * 32 + j0) = o;
                }
            }
        }
    } else {
        // ---- warp 4: MMA issuer (2 dispatches per K-chunk: M halves) ----
        uint32_t ep = elect_one();
        int s = 0; uint32_t ph = 0;
        for (int kt = 0; kt < nk; kt++) {
            mbar_wait(sb + OFF_FULL(s), ph);
            if (ep) {
                const uint32_t st = sb + 1024 + s * STAGE_BYTES;
                uint64_t ad0 = make_desc(st);
                uint64_t ad1 = make_desc(st + 16384);
                uint64_t bd  = make_desc(st + 32768);
                const uint32_t en0 = (uint32_t)(kt != 0);
                #pragma unroll
                for (int j = 0; j < 4; j++) {
                    const uint32_t en = en0 | (uint32_t)(j != 0);
                    mma_tf32(tmem,       ad0 + 2 * j, bd + 2 * j, IDESC, en);
                    mma_tf32(tmem + 256, ad1 + 2 * j, bd + 2 * j, IDESC, en);
                }
                if (kt == nk - 1) TC_COMMIT(sb + OFF_FIN);
                else              TC_COMMIT(sb + OFF_EMPTY(s));
            }
            if (++s == NS) { s = 0; ph ^= 1; }
        }
    }

    __syncthreads();
    if (wid == 4) TC_DEALLOC(tmem, 512);
#endif // HAS_TC
}

// ---------------- elementwise kernels ---------------------------------------
__device__ __forceinline__ float block_sum(float v, float* sh) {
    const int lane = threadIdx.x & 31, w = threadIdx.x >> 5;
    #pragma unroll
    for (int o = 16; o; o >>= 1) v += __shfl_xor_sync(0xffffffffu, v, o);
    __syncthreads();
    if (lane == 0) sh[w] = v;
    __syncthreads();
    float s = 0.f;
    #pragma unroll
    for (int i = 0; i < 8; i++) s += sh[i];
    return s;
}
__device__ __forceinline__ float block_max(float v, float* sh) {
    const int lane = threadIdx.x & 31, w = threadIdx.x >> 5;
    #pragma unroll
    for (int o = 16; o; o >>= 1) v = fmaxf(v, __shfl_xor_sync(0xffffffffu, v, o));
    __syncthreads();
    if (lane == 0) sh[w] = v;
    __syncthreads();
    float s = -INFINITY;
    #pragma unroll
    for (int i = 0; i < 8; i++) s = fmaxf(s, sh[i]);
    return s;
}

__global__ void __launch_bounds__(256) softmax_kernel(float* __restrict__ data)
{
    __shared__ float sh[8];
    const long long row = blockIdx.x;
    float4* p = reinterpret_cast<float4*>(data + row * 1024);
    float4 x = p[threadIdx.x];
    float m = fmaxf(fmaxf(x.x, x.y), fmaxf(x.z, x.w));
    m = block_max(m, sh);
    x.x = expf(x.x - m); x.y = expf(x.y - m);
    x.z = expf(x.z - m); x.w = expf(x.w - m);
    float s = x.x + x.y + x.z + x.w;
    s = block_sum(s, sh);
    const float inv = 1.0f / s;
    x.x = rna_tf32(x.x * inv); x.y = rna_tf32(x.y * inv);
    x.z = rna_tf32(x.z * inv); x.w = rna_tf32(x.w * inv);
    p[threadIdx.x] = x;
}

template<bool ROUND>
__global__ void __launch_bounds__(256)
ln_kernel(const float* __restrict__ in, const float* __restrict__ g,
          const float* __restrict__ b, float* __restrict__ out)
{
    __shared__ float sh[8];
    const long long row = blockIdx.x;
    const float4* p = reinterpret_cast<const float4*>(in + row * 1024);
    float4 x = p[threadIdx.x];
    float s = x.x + x.y + x.z + x.w;
    s = block_sum(s, sh);
    const float mu = s * (1.0f / 1024.0f);
    const float dx = x.x - mu, dy = x.y - mu, dz = x.z - mu, dw = x.w - mu;
    float ss = dx * dx + dy * dy + dz * dz + dw * dw;
    ss = block_sum(ss, sh);
    const float rstd = rsqrtf(ss * (1.0f / 1024.0f) + 1e-12f);
    const float4 gg = reinterpret_cast<const float4*>(g)[threadIdx.x];
    const float4 bb = reinterpret_cast<const float4*>(b)[threadIdx.x];
    float4 o;
    o.x = dx * rstd * gg.x + bb.x;
    o.y = dy * rstd * gg.y + bb.y;
    o.z = dz * rstd * gg.z + bb.z;
    o.w = dw * rstd * gg.w + bb.w;
    if (ROUND) { o.x = rna_tf32(o.x); o.y = rna_tf32(o.y); o.z = rna_tf32(o.z); o.w = rna_tf32(o.w); }
    reinterpret_cast<float4*>(out + row * 1024)[threadIdx.x] = o;
}

// Fast 64x64 transpose: out[c, r] = (rna) in[r, c]; batched via z.
// in is [R, C]; launch grid = (C/64, R/64, batch).
template<bool ROUND>
__global__ void __launch_bounds__(256)
transpose_fast(const float* __restrict__ in, float* __restrict__ out,
               int R, int C, long long sIn, long long sOut)
{
    __shared__ float t[64][65];
    in  += blockIdx.z * sIn;
    out += blockIdx.z * sOut;
    const int r0 = blockIdx.y * 64, c0 = blockIdx.x * 64;
    const int fc = (threadIdx.x & 15) * 4;   // 0..60
    const int fr = threadIdx.x >> 4;         // 0..15

    #pragma unroll
    for (int i = 0; i < 4; i++) {
        const int r = fr + i * 16;
        float4 x = *reinterpret_cast<const float4*>(in + (long long)(r0 + r) * C + c0 + fc);
        t[fc + 0][r] = x.x; t[fc + 1][r] = x.y; t[fc + 2][r] = x.z; t[fc + 3][r] = x.w;
    }
    __syncthreads();
    #pragma unroll
    for (int i = 0; i < 4; i++) {
        const int oc = fr + i * 16;
        float4 y;
        y.x = t[oc][fc + 0]; y.y = t[oc][fc + 1];
        y.z = t[oc][fc + 2]; y.w = t[oc][fc + 3];
        if (ROUND) {
            y.x = rna_tf32(y.x); y.y = rna_tf32(y.y);
            y.z = rna_tf32(y.z); y.w = rna_tf32(y.w);
        }
        *reinterpret_cast<float4*>(out + (long long)(c0 + oc) * R + r0 + fc) = y;
    }
}

__global__ void __launch_bounds__(256)
round_kernel(const float4* __restrict__ in, float4* __restrict__ out, long long n4)
{
    for (long long i = blockIdx.x * 256LL + threadIdx.x; i < n4; i += gridDim.x * 256LL) {
        float4 v = in[i];
        v.x = rna_tf32(v.x); v.y = rna_tf32(v.y);
        v.z = rna_tf32(v.z); v.w = rna_tf32(v.w);
        out[i] = v;
    }
}

__global__ void __launch_bounds__(1024)
bias2_kernel(const float* __restrict__ b0, const float* __restrict__ b1,
             float* __restrict__ out)
{
    const float* src = blockIdx.x == 0 ? b0 : b1;
    out[blockIdx.x * 1024 + threadIdx.x] = src[threadIdx.x];
}

// ---------------- host launcher -----------------------------------------------
extern "C" void kernel_launch(void* const* d_in, const int* in_sizes, int n_in,
                              void* d_out, int out_size)
{
    const float* x  = (const float*)d_in[0];
    const float* Wq = (const float*)d_in[1];
    const float* bq = (const float*)d_in[2];
    const float* Wk = (const float*)d_in[3];
    const float* bk = (const float*)d_in[4];
    const float* Wv = (const float*)d_in[5];
    const float* bv = (const float*)d_in[6];
    const float* Wd = (const float*)d_in[7];
    const float* bd = (const float*)d_in[8];
    const float* g1 = (const float*)d_in[9];
    const float* b1 = (const float*)d_in[10];
    const float* Wi = (const float*)d_in[11];
    const float* bi = (const float*)d_in[12];
    const float* Wo = (const float*)d_in[13];
    const float* bo = (const float*)d_in[14];
    const float* g2 = (const float*)d_in[15];
    const float* b2 = (const float*)d_in[16];
    float* out = (float*)d_out;

    float *xr, *qk, *vt, *at, *ao, *tmp, *h1, *ff;
    float *wt, *b2qk, *wdt, *wit, *wot;
    cudaGetSymbolAddress((void**)&xr,   g_xr);
    cudaGetSymbolAddress((void**)&qk,   g_qk);
    cudaGetSymbolAddress((void**)&vt,   g_vt);
    cudaGetSymbolAddress((void**)&at,   g_at);
    cudaGetSymbolAddress((void**)&ao,   g_ao);
    cudaGetSymbolAddress((void**)&tmp,  g_tmp);
    cudaGetSymbolAddress((void**)&h1,   g_h1);
    cudaGetSymbolAddress((void**)&ff,   g_ff);
    cudaGetSymbolAddress((void**)&wt,   g_wt);
    cudaGetSymbolAddress((void**)&b2qk, g_b2);
    cudaGetSymbolAddress((void**)&wdt,  g_wdt);
    cudaGetSymbolAddress((void**)&wit,  g_wit);
    cudaGetSymbolAddress((void**)&wot,  g_wot);

    cudaFuncSetAttribute(tc_gemm<0, true,  false>, cudaFuncAttributeMaxDynamicSharedMemorySize, SMEM_TOTAL);
    cudaFuncSetAttribute(tc_gemm<0, true,  true >, cudaFuncAttributeMaxDynamicSharedMemorySize, SMEM_TOTAL);
    cudaFuncSetAttribute(tc_gemm<0, false, false>, cudaFuncAttributeMaxDynamicSharedMemorySize, SMEM_TOTAL);
    cudaFuncSetAttribute(tc_gemm<1, true,  false>, cudaFuncAttributeMaxDynamicSharedMemorySize, SMEM_TOTAL);

    const long long ME = (long long)MTOT * Ed;
    const long long SE = (long long)Sd * Ed;
    const long long SS = (long long)Sd * Sd;
    const long long EE = (long long)Ed * Ed;
    float* q = qk;
    float* k = qk + ME;
    const dim3 tb(256);
    const dim3 gt(160);

    // 0-4: prep
    round_kernel<<<256, tb>>>((const float4*)x, (float4*)xr, ME / 4);
    transpose_fast<true><<<dim3(Ed/64, Ed/64, 1), tb>>>(Wq, wt,          Ed, Ed, 0, 0);
    transpose_fast<true><<<dim3(Ed/64, Ed/64, 1), tb>>>(Wk, wt + EE,     Ed, Ed, 0, 0);
    transpose_fast<true><<<dim3(Ed/64, Ed/64, 1), tb>>>(Wv, wt + 2 * EE, Ed, Ed, 0, 0);
    bias2_kernel<<<2, 1024>>>(bq, bk, b2qk);

    // 5: fused Q,K projections (grid.z selects weight/bias/output)
    tc_gemm<0, true, false><<<dim3(Ed/TN, MTOT/TMM, 2), gt, SMEM_TOTAL>>>(
        xr, wt, b2qk, nullptr, qk, Ed, Ed, 1.0f, 0, EE, ME, Ed);

    // 6: vt = Wv^T @ x^T + bv (per batch) -> [E, S], row-bias epilogue
    tc_gemm<0, true, true><<<dim3(Sd/TN, Ed/TMM, Bd), gt, SMEM_TOTAL>>>(
        wt + 2 * EE, xr, bv, nullptr, vt, Ed, Sd, 1.0f, 0, SE, SE, 0);

    // 7: scores = q @ k^T / 32 (batched over B)
    tc_gemm<0, false, false><<<dim3(Sd/TN, Sd/TMM, Bd), gt, SMEM_TOTAL>>>(
        q, k, nullptr, nullptr, at, Ed, Sd, 0.03125f, SE, SE, SS, 0);

    // 8: softmax (RNA-rounded)
    softmax_kernel<<<Bd * Sd, tb>>>(at);

    // 9: attn_out = attn_w @ v   (Bt = vt, already [E, S] K-major)
    tc_gemm<0, true, false><<<dim3(Ed/TN, Sd/TMM, Bd), gt, SMEM_TOTAL>>>(
        at, vt, nullptr, nullptr, ao, Sd, Ed, 1.0f, SS, SE, SE, 0);

    // 10-12: Wd GEMM (+bias +resid x) then LN1
    transpose_fast<true><<<dim3(Ed/64, Ed/64, 1), tb>>>(Wd, wdt, Ed, Ed, 0, 0);
    tc_gemm<0, false, false><<<dim3(Ed/TN, MTOT/TMM, 1), gt, SMEM_TOTAL>>>(
        ao, wdt, bd, x, tmp, Ed, Ed, 1.0f, 0, 0, 0, 0);
    ln_kernel<true><<<MTOT, tb>>>(tmp, g1, b1, h1);

    // 13-14: ff = gelu(h1 @ Wi + bi). Wi is [Ed, Fd] -> grid (Fd/64, Ed/64).
    transpose_fast<true><<<dim3(Fd/64, Ed/64, 1), tb>>>(Wi, wit, Ed, Fd, 0, 0);
    tc_gemm<1, true, false><<<dim3(Fd/TN, MTOT/TMM, 1), gt, SMEM_TOTAL>>>(
        h1, wit, bi, nullptr, ff, Ed, Fd, 1.0f, 0, 0, 0, 0);

    // 15-17: out = LN(ff @ Wo + bo + h1). Wo is [Fd, Ed] -> grid (Ed/64, Fd/64).
    transpose_fast<true><<<dim3(Ed/64, Fd/64, 1), tb>>>(Wo, wot, Fd, Ed, 0, 0);
    tc_gemm<0, false, false><<<dim3(Ed/TN, MTOT/TMM, 1), gt, SMEM_TOTAL>>>(
        ff, wot, bo, h1, tmp, Fd, Ed, 1.0f, 0, 0, 0, 0);
    ln_kernel<false><<<MTOT, tb>>>(tmp, g2, b2, out);
}